// round 14
// baseline (speedup 1.0000x reference)
#include <cuda_runtime.h>
#include <cstdint>

// MonarchOutProjection:
//   h2[t][m][q]   = sum_k L[m][q][k] * x[t][32k+m]
//   out[t][32p+q] = sum_m R[q][p][m] * h2[t][m][q]
//
// R7: grid (37,4) = 148 persistent CTAs, 8 q per CTA, 128-token tiles.
//  - Stage1: warp w: all 8 q (Qw=8), pairs [4w,4w+4) (Pw=4) -> 0.5 wf/ffma2.
//    x LDG'd straight to regs, double-buffered kk=2 chunks.
//  - Stage2: warp w: q=w>>1, pair-block s=w&1; R[q] cached in 64 regs;
//    h read as float4 broadcasts; 4 phases of 8 pairs each (acc = 16 regs).
//  - outs staging XOR-swizzled (p ^ (q<<2)): conflict-free, no padding.
//  - smem: Ls 32KB + Rs 32KB + h2 128KB + outs 32KB = 229376 B.

#define THREADS 512
#define GRIDX   37
#define TPT     128

#define OFF_LS   0          // Ls[q*1024 + k*32 + m]        8192 f
#define OFF_RS   8192       // Rs[q*1024 + m*32 + p]        8192 f
#define OFF_H2   16384      // f2[(q*64 + pair)*32 + m]    16384 f2 = 32768 f
#define OFF_OUT  49152      // outs[t2*256 + q*32 + (p^(q<<2))]  8192 f
#define SMEM_FLOATS 57344
#define SMEM_BYTES  (SMEM_FLOATS * 4)   // 229376 B

typedef unsigned long long ull;

__device__ __forceinline__ ull pack2(float v) {
    ull r; asm("mov.b64 %0, {%1, %1};" : "=l"(r) : "f"(v)); return r;
}
__device__ __forceinline__ ull packpair(float a, float b) {
    ull r; asm("mov.b64 %0, {%1, %2};" : "=l"(r) : "f"(a), "f"(b)); return r;
}
__device__ __forceinline__ ull ffma2(ull a, ull b, ull c) {
    ull d; asm("fma.rn.f32x2 %0, %1, %2, %3;" : "=l"(d) : "l"(a), "l"(b), "l"(c));
    return d;
}
__device__ __forceinline__ void unpack2(ull v, float& lo, float& hi) {
    asm("mov.b64 {%0, %1}, %2;" : "=f"(lo), "=f"(hi) : "l"(v));
}

__global__ __launch_bounds__(THREADS, 1)
void monarch_kernel(const float* __restrict__ x,
                    const float* __restrict__ Lg,
                    const float* __restrict__ Rg,
                    float* __restrict__ out,
                    int ntiles)
{
    extern __shared__ float sm[];
    float*  Ls   = sm + OFF_LS;
    float*  Rs   = sm + OFF_RS;
    float2* h2   = (float2*)(sm + OFF_H2);
    float*  outs = sm + OFF_OUT;

    const int tid  = threadIdx.x;
    const int w    = tid >> 5;
    const int lane = tid & 31;
    const int qb   = blockIdx.y * 8;

    // ---- one-time weight staging (coalesced LDG; STS conflicts amortized) ----
    // Ls[q*1024 + k*32 + m] = Lg[m*1024 + (qb+q)*32 + k]
    for (int j = tid; j < 8192; j += THREADS) {
        int m = j >> 8;                 // 0..31
        int r = j & 255;                // q*32 + k
        Ls[(r >> 5) * 1024 + (r & 31) * 32 + m] = Lg[m * 1024 + qb * 32 + r];
    }
    // Rs[q*1024 + m*32 + p] = Rg[(qb+q)*1024 + p*32 + m]
    for (int j = tid; j < 8192; j += THREADS) {
        int q = j >> 10;
        int r = j & 1023;               // p*32 + m
        Rs[q * 1024 + (r & 31) * 32 + (r >> 5)] = Rg[(qb + q) * 1024 + r];
    }
    __syncthreads();

    int tile = blockIdx.x;

    // x register double buffer: xr[buf][tok*2 + kk], tokens [8w, 8w+8), kk chunk=2
    float xr[2][16];
    {
        int pt = (tile < ntiles) ? tile : 0;
        const float* pb = x + (size_t)(pt * TPT + 8 * w) * 1024 + lane;
        #pragma unroll
        for (int t = 0; t < 8; t++)
            #pragma unroll
            for (int kk = 0; kk < 2; kk++)
                xr[0][t * 2 + kk] = pb[t * 1024 + kk * 32];
    }

    for (; tile < ntiles; tile += GRIDX) {
        // ===================== stage 1 =====================
        ull acc[8][4];
        #pragma unroll
        for (int qs = 0; qs < 8; qs++)
            #pragma unroll
            for (int pr = 0; pr < 4; pr++) acc[qs][pr] = 0ull;

        const float* Lbase = Ls + lane;

        #pragma unroll 2
        for (int c = 0; c < 16; c++) {
            const int cb = c & 1;
            // prefetch next chunk (or next tile chunk 0), clamped
            {
                int  ptile = (c < 15) ? tile : (tile + GRIDX);
                int  pk    = (c < 15) ? 2 * (c + 1) : 0;
                int  st    = (ptile < ntiles) ? ptile : 0;
                const float* pb = x + (size_t)(st * TPT + 8 * w) * 1024
                                    + pk * 32 + lane;
                #pragma unroll
                for (int t = 0; t < 8; t++)
                    #pragma unroll
                    for (int kk = 0; kk < 2; kk++)
                        xr[cb ^ 1][t * 2 + kk] = pb[t * 1024 + kk * 32];
            }
            // compute k = 2c, 2c+1
            #pragma unroll
            for (int kk = 0; kk < 2; kk++) {
                const int k = 2 * c + kk;
                ull v[4];
                #pragma unroll
                for (int pr = 0; pr < 4; pr++)
                    v[pr] = packpair(xr[cb][(2 * pr) * 2 + kk],
                                     xr[cb][(2 * pr + 1) * 2 + kk]);
                const float* Lp = Lbase + k * 32;
                #pragma unroll
                for (int qs = 0; qs < 8; qs++) {
                    ull Lq = pack2(Lp[qs * 1024]);
                    #pragma unroll
                    for (int pr = 0; pr < 4; pr++)
                        acc[qs][pr] = ffma2(Lq, v[pr], acc[qs][pr]);
                }
            }
        }

        // h2[(q*64 + pair)*32 + m] <- acc  (8B STS, conflict-free)
        #pragma unroll
        for (int qs = 0; qs < 8; qs++)
            #pragma unroll
            for (int pr = 0; pr < 4; pr++)
                *(ull*)&h2[(qs * 64 + 4 * w + pr) * 32 + lane] = acc[qs][pr];
        __syncthreads();                 // h2 complete

        // ===================== stage 2 =====================
        const int q2 = w >> 1;           // local q
        const int s2 = w & 1;            // pair-block within phase
        const int myx = lane ^ (q2 << 2);

        // R cache: 32 ull (reloaded per tile; 32 LDS amortized over 2048 ffma2)
        ull rr[32];
        {
            const float* Rp = Rs + q2 * 1024 + lane;
            #pragma unroll
            for (int m = 0; m < 32; m++) rr[m] = pack2(Rp[m * 32]);
        }

        #pragma unroll
        for (int ph = 0; ph < 4; ph++) {
            const int gp0 = 16 * ph + 8 * s2;        // first pair of this warp
            ull a2[8];
            #pragma unroll
            for (int j = 0; j < 8; j++) a2[j] = 0ull;

            const float4* hq = (const float4*)(h2 + (q2 * 64 + gp0) * 32);
            #pragma unroll 4
            for (int m = 0; m < 32; m += 2) {
                #pragma unroll
                for (int j = 0; j < 8; j++) {
                    float4 hh = hq[(j * 32 + m) >> 1];
                    a2[j] = ffma2(rr[m],     packpair(hh.x, hh.y), a2[j]);
                    a2[j] = ffma2(rr[m + 1], packpair(hh.z, hh.w), a2[j]);
                }
            }
            // outs[t2*256 + q*32 + (p ^ (q<<2))], t2 in [0,32) within phase
            #pragma unroll
            for (int j = 0; j < 8; j++) {
                float f0, f1; unpack2(a2[j], f0, f1);
                int t2 = 2 * (8 * s2 + j);
                outs[(t2    ) * 256 + q2 * 32 + myx] = f0;
                outs[(t2 + 1) * 256 + q2 * 32 + myx] = f1;
            }
            __syncthreads();             // outs complete

            // writeout: 32 tokens (tile*128 + 32ph + t2)
            {
                const size_t gb = ((size_t)tile * TPT + 32 * ph) * 1024 + qb;
                #pragma unroll
                for (int i = 0; i < 16; i++) {
                    int lin = tid + i * THREADS;       // < 8192
                    int t2  = lin >> 8;
                    int rem = lin & 255;
                    int p   = rem >> 3;
                    int qq  = rem & 7;
                    out[gb + (size_t)t2 * 1024 + p * 32 + qq] =
                        outs[t2 * 256 + qq * 32 + (p ^ (qq << 2))];
                }
            }
            __syncthreads();             // outs reusable / h2 safe after ph3
        }
    }
}

extern "C" void kernel_launch(void* const* d_in, const int* in_sizes, int n_in,
                              void* d_out, int out_size)
{
    const float* x  = (const float*)d_in[0];
    const float* Lg = (const float*)d_in[1];
    const float* Rg = (const float*)d_in[2];
    float* out      = (float*)d_out;

    const int tokens = in_sizes[0] / 1024;   // 32768
    const int ntiles = tokens / TPT;         // 256

    cudaFuncSetAttribute(monarch_kernel,
                         cudaFuncAttributeMaxDynamicSharedMemorySize, SMEM_BYTES);

    dim3 grid(GRIDX, 4);
    monarch_kernel<<<grid, THREADS, SMEM_BYTES>>>(x, Lg, Rg, out, ntiles);
}

// round 15
// speedup vs baseline: 1.0766x; 1.0766x over previous
#include <cuda_runtime.h>
#include <cstdint>

// MonarchOutProjection:
//   h2[t][m][q]   = sum_k L[m][q][k] * x[t][32k+m]
//   out[t][32p+q] = sum_m R[q][p][m] * h2[t][m][q]
//
// R8: stall-bound fix -> 24 warps/SM (6 per SMSP), keep R6 reuse ratios.
//  - grid (37,4) = 148 persistent CTAs, 8 q per CTA, 96-token tiles (tail clamped).
//  - 768 threads. Stage1: warp w: all 8 q (Qw=8), pairs {2w,2w+1} (Pw=2);
//    acc = 16 ull (32 regs), x LDG'd to regs, double-buffered 2-k chunks.
//  - Stage2: warp w: q=w&7, third sg=w>>3; 2 phases x 8 pairs (a2 = 16 regs);
//    R loaded per-m as lane-vector (reused over 8 pairs), h as float4 broadcasts.
//  - outs XOR-swizzled (p ^ (q<<2)): conflict-free STS and LDS, no padding.
//  - smem: Ls 32K + Rs 32K + h2 96K + outs 48K = 212992 B. 4 syncs/tile.

#define THREADS 768
#define GRIDX   37
#define TPT     96
#define TOTAL_TOK 32768

#define OFF_LS   0          // Ls[q*1024 + k*32 + m]              8192 f
#define OFF_RS   8192       // Rs[q*1024 + m*32 + p]              8192 f
#define OFF_H2   16384      // f2[(q*48 + pair)*32 + m]          12288 f2
#define OFF_OUT  40960      // outs[t*256 + q*32 + (p^(q<<2))]   12288 f
#define SMEM_FLOATS 53248
#define SMEM_BYTES  (SMEM_FLOATS * 4)   // 212992 B

typedef unsigned long long ull;

__device__ __forceinline__ ull pack2(float v) {
    ull r; asm("mov.b64 %0, {%1, %1};" : "=l"(r) : "f"(v)); return r;
}
__device__ __forceinline__ ull packpair(float a, float b) {
    ull r; asm("mov.b64 %0, {%1, %2};" : "=l"(r) : "f"(a), "f"(b)); return r;
}
__device__ __forceinline__ ull ffma2(ull a, ull b, ull c) {
    ull d; asm("fma.rn.f32x2 %0, %1, %2, %3;" : "=l"(d) : "l"(a), "l"(b), "l"(c));
    return d;
}
__device__ __forceinline__ void unpack2(ull v, float& lo, float& hi) {
    asm("mov.b64 {%0, %1}, %2;" : "=f"(lo), "=f"(hi) : "l"(v));
}

__global__ __launch_bounds__(THREADS, 1)
void monarch_kernel(const float* __restrict__ x,
                    const float* __restrict__ Lg,
                    const float* __restrict__ Rg,
                    float* __restrict__ out,
                    int ntiles)
{
    extern __shared__ float sm[];
    float*  Ls   = sm + OFF_LS;
    float*  Rs   = sm + OFF_RS;
    float2* h2   = (float2*)(sm + OFF_H2);
    float*  outs = sm + OFF_OUT;

    const int tid  = threadIdx.x;
    const int w    = tid >> 5;
    const int lane = tid & 31;
    const int qb   = blockIdx.y * 8;

    // ---- one-time weight staging ----
    // Ls[q*1024 + k*32 + m] = Lg[m*1024 + (qb+q)*32 + k]
    for (int j = tid; j < 8192; j += THREADS) {
        int m = j >> 8;                 // 0..31
        int r = j & 255;                // q*32 + k
        Ls[(r >> 5) * 1024 + (r & 31) * 32 + m] = Lg[m * 1024 + qb * 32 + r];
    }
    // Rs[q*1024 + m*32 + p] = Rg[(qb+q)*1024 + p*32 + m]
    for (int j = tid; j < 8192; j += THREADS) {
        int q = j >> 10;
        int r = j & 1023;               // p*32 + m
        Rs[q * 1024 + (r & 31) * 32 + (r >> 5)] = Rg[(qb + q) * 1024 + r];
    }
    __syncthreads();

    int tile = blockIdx.x;

    // x register double buffer: xr[buf][t*2 + kk], tokens {4w..4w+3}, 2-k chunks
    float xr[2][8];
    {
        int st = (tile < ntiles) ? tile : 0;
        int tb = st * TPT + 4 * w;
        if (tb > TOTAL_TOK - 4) tb = TOTAL_TOK - 4;     // tail clamp
        const float* pb = x + (size_t)tb * 1024 + lane;
        #pragma unroll
        for (int t = 0; t < 4; t++)
            #pragma unroll
            for (int kk = 0; kk < 2; kk++)
                xr[0][t * 2 + kk] = pb[t * 1024 + kk * 32];
    }

    for (; tile < ntiles; tile += GRIDX) {
        // ===================== stage 1 =====================
        ull acc[8][2];
        #pragma unroll
        for (int qs = 0; qs < 8; qs++) { acc[qs][0] = 0ull; acc[qs][1] = 0ull; }

        const float* Lbase = Ls + lane;

        #pragma unroll 4
        for (int c = 0; c < 16; c++) {
            const int cb = c & 1;
            // prefetch next 2-k chunk (or next tile chunk 0), clamped
            {
                int ptile = (c < 15) ? tile : (tile + GRIDX);
                int pk    = (c < 15) ? 2 * (c + 1) : 0;
                int st    = (ptile < ntiles) ? ptile : 0;
                int tb    = st * TPT + 4 * w;
                if (tb > TOTAL_TOK - 4) tb = TOTAL_TOK - 4;
                const float* pb = x + (size_t)tb * 1024 + pk * 32 + lane;
                #pragma unroll
                for (int t = 0; t < 4; t++)
                    #pragma unroll
                    for (int kk = 0; kk < 2; kk++)
                        xr[cb ^ 1][t * 2 + kk] = pb[t * 1024 + kk * 32];
            }
            // compute k = 2c, 2c+1
            #pragma unroll
            for (int kk = 0; kk < 2; kk++) {
                const int k = 2 * c + kk;
                ull v0 = packpair(xr[cb][0 * 2 + kk], xr[cb][1 * 2 + kk]);
                ull v1 = packpair(xr[cb][2 * 2 + kk], xr[cb][3 * 2 + kk]);
                const float* Lp = Lbase + k * 32;
                #pragma unroll
                for (int qs = 0; qs < 8; qs++) {
                    ull Lq = pack2(Lp[qs * 1024]);
                    acc[qs][0] = ffma2(Lq, v0, acc[qs][0]);
                    acc[qs][1] = ffma2(Lq, v1, acc[qs][1]);
                }
            }
        }

        // h2[(q*48 + pair)*32 + m] <- acc   (pair = 2w+pr, tokens {2pair,2pair+1})
        #pragma unroll
        for (int qs = 0; qs < 8; qs++)
            #pragma unroll
            for (int pr = 0; pr < 2; pr++)
                *(ull*)&h2[(qs * 48 + 2 * w + pr) * 32 + lane] = acc[qs][pr];
        __syncthreads();                 // sync1: h2 complete (prev writeout done)

        // ===================== stage 2 (2 phases x 48 tokens) =====================
        const int q2  = w & 7;
        const int sg  = w >> 3;          // 0..2: 8-pair block within phase
        const int myx = lane ^ (q2 << 2);
        const float* Rp = Rs + q2 * 1024 + lane;

        #pragma unroll
        for (int ph = 0; ph < 2; ph++) {
            ull a2[8];
            #pragma unroll
            for (int j = 0; j < 8; j++) a2[j] = 0ull;

            const float4* hqb = (const float4*)h2
                              + (q2 * 48 + 24 * ph + 8 * sg) * 16;
            #pragma unroll 4
            for (int m = 0; m < 32; m += 2) {
                ull R0 = pack2(Rp[m * 32]);
                ull R1 = pack2(Rp[(m + 1) * 32]);
                #pragma unroll
                for (int j = 0; j < 8; j++) {
                    float4 hh = hqb[j * 16 + (m >> 1)];
                    a2[j] = ffma2(R0, packpair(hh.x, hh.y), a2[j]);
                    a2[j] = ffma2(R1, packpair(hh.z, hh.w), a2[j]);
                }
            }
            // outs[t'*256 + q*32 + (p ^ (q<<2))], t' in [0,48)
            #pragma unroll
            for (int j = 0; j < 8; j++) {
                float f0, f1; unpack2(a2[j], f0, f1);
                int tp = 2 * (8 * sg + j);
                outs[(tp    ) * 256 + q2 * 32 + myx] = f0;
                outs[(tp + 1) * 256 + q2 * 32 + myx] = f1;
            }
            __syncthreads();             // sync2/4: outs complete

            // writeout: 48 tokens (tile*96 + 48ph + t'), guarded for tail
            {
                const int gt0 = tile * TPT + 48 * ph;
                #pragma unroll
                for (int i = 0; i < 16; i++) {
                    int lin = tid + i * THREADS;       // < 12288
                    int t   = lin >> 8;
                    int rem = lin & 255;
                    int p   = rem >> 3;
                    int qq  = rem & 7;
                    int gt  = gt0 + t;
                    float v = outs[t * 256 + qq * 32 + (p ^ (qq << 2))];
                    if (gt < TOTAL_TOK)
                        out[(size_t)gt * 1024 + p * 32 + qb + qq] = v;
                }
            }
            __syncthreads();             // sync3/5: outs reusable / h2 safe
        }
    }
}

extern "C" void kernel_launch(void* const* d_in, const int* in_sizes, int n_in,
                              void* d_out, int out_size)
{
    const float* x  = (const float*)d_in[0];
    const float* Lg = (const float*)d_in[1];
    const float* Rg = (const float*)d_in[2];
    float* out      = (float*)d_out;

    const int tokens = in_sizes[0] / 1024;            // 32768
    const int ntiles = (tokens + TPT - 1) / TPT;      // 342 (tail clamped)

    cudaFuncSetAttribute(monarch_kernel,
                         cudaFuncAttributeMaxDynamicSharedMemorySize, SMEM_BYTES);

    dim3 grid(GRIDX, 4);
    monarch_kernel<<<grid, THREADS, SMEM_BYTES>>>(x, Lg, Rg, out, ntiles);
}